// round 14
// baseline (speedup 1.0000x reference)
#include <cuda_runtime.h>
#include <cuda_fp16.h>
#include <cstdint>

#define SEQ 2048
#define INF 1024
#define HID 2048
#define OUT 1024
#define NCTA 128
#define FULL 0xffffffffu

// Scratch (device globals — allocation-free per harness rules)
__device__ float g_gx[3][(size_t)SEQ * HID];  // precomputed Wx@x_t + b, per gate
// Flag-in-data exchange slots (CONCENTRATED layout — R11-proven).
// Slot s = (b, m): b = producer CTA, m = 0..3.
// uint4 = {lo, tag, hi, tag}: lo = halves {16b+2m, 16b+2m+1},
//                             hi = halves {16b+2m+8, 16b+2m+9}
__device__ uint4 g_hx[NCTA * 4];    // h exchange   (tag = t+1 for step-t use)
__device__ uint4 g_rhx[NCTA * 4];   // r*h exchange (tag = t+1 at step t)

// ---------------------------------------------------------------------------
__global__ void reset_state() {   // zero all slot tags each launch (replay-safe)
    int i = blockIdx.x * blockDim.x + threadIdx.x;
    if (i < NCTA * 4) {
        g_hx[i]  = make_uint4(0u, 0u, 0u, 0u);
        g_rhx[i] = make_uint4(0u, 0u, 0u, 0u);
    }
}

#define POLL_LD(X, Y, Z, W, P)                                              \
    asm volatile("ld.relaxed.gpu.global.v4.b32 {%0,%1,%2,%3}, [%4];"        \
                 : "=r"(X), "=r"(Y), "=r"(Z), "=r"(W) : "l"(P) : "memory")

// Staggered double-poll: two in-flight loads phase-shifted ~half the poll
// period, checked alternately -> observation granularity ~RT/2 instead of RT.
// Fast path (already published) is a single load.
__device__ __forceinline__ uint2 poll_slot(const uint4* p, unsigned tag) {
    unsigned x0, y0, z0, w0;
    POLL_LD(x0, y0, z0, w0, p);
    if (y0 == tag && w0 == tag) return make_uint2(x0, z0);
    unsigned x1, y1, z1, w1;
    POLL_LD(x0, y0, z0, w0, p);          // reissue A
    {                                     // ~130-cycle dependent-ALU stagger
        unsigned d = 0;
#pragma unroll
        for (int i = 0; i < 32; ++i)
            asm volatile("add.u32 %0, %0, 1;" : "+r"(d));
    }
    POLL_LD(x1, y1, z1, w1, p);          // issue B, half-period behind A
    for (;;) {
        if (y0 == tag && w0 == tag) return make_uint2(x0, z0);
        POLL_LD(x0, y0, z0, w0, p);
        if (y1 == tag && w1 == tag) return make_uint2(x1, z1);
        POLL_LD(x1, y1, z1, w1, p);
    }
}

__device__ __forceinline__ void publish_slot(uint4* p, unsigned lo, unsigned hi,
                                             unsigned tag) {
    asm volatile("st.release.gpu.global.v4.b32 [%0], {%1,%2,%3,%4};"
                 :: "l"(p), "r"(lo), "r"(tag), "r"(hi), "r"(tag) : "memory");
}

__device__ __forceinline__ void mma16816(
    float& c0, float& c1, float& c2, float& c3,
    unsigned a0, unsigned a1, unsigned a2, unsigned a3,
    unsigned b0, unsigned b1)
{
    asm volatile(
        "mma.sync.aligned.m16n8k16.row.col.f32.f16.f16.f32 "
        "{%0,%1,%2,%3}, {%4,%5,%6,%7}, {%8,%9}, {%0,%1,%2,%3};"
        : "+f"(c0), "+f"(c1), "+f"(c2), "+f"(c3)
        : "r"(a0), "r"(a1), "r"(a2), "r"(a3), "r"(b0), "r"(b1));
}

// ---------------------------------------------------------------------------
// fp16 tensor-core GEMM with register-pipelined staging (R13-proven).
// ---------------------------------------------------------------------------
#define GBM 128
#define GBN 64
#define GBK 64
#define GST 36

__device__ __forceinline__ void hgemm_body(
    const float* __restrict__ A, int lda,
    const float* __restrict__ B, int ldb,
    const float* __restrict__ bias,
    float* __restrict__ C, int ldc, int K,
    int bm, int bn)
{
    __shared__ unsigned As[GBM * GST];
    __shared__ unsigned Bs[GBN * GST];

    const int tid = threadIdx.x;
    const int wid = tid >> 5;
    const int l   = tid & 31;
    const int r   = l >> 2;
    const int m   = l & 3;
    const int wm  = (wid & 3) * 32;
    const int wn  = (wid >> 2) * 32;
    const int srow = tid >> 4;
    const int c4   = tid & 15;

    float acc[2][4][4];
#pragma unroll
    for (int i = 0; i < 2; ++i)
#pragma unroll
        for (int j = 0; j < 4; ++j)
#pragma unroll
            for (int k = 0; k < 4; ++k) acc[i][j][k] = 0.f;

    float4 ra[8];
    float4 rb[4];

#pragma unroll
    for (int j = 0; j < 8; ++j)
        ra[j] = *(const float4*)(A + (size_t)(bm + srow + 16 * j) * lda + c4 * 4);
#pragma unroll
    for (int j = 0; j < 4; ++j)
        rb[j] = *(const float4*)(B + (size_t)(bn + srow + 16 * j) * ldb + c4 * 4);

    for (int k0 = 0; k0 < K; k0 += GBK) {
#pragma unroll
        for (int j = 0; j < 8; ++j) {
            __half2 p0 = __floats2half2_rn(ra[j].x, ra[j].y);
            __half2 p1 = __floats2half2_rn(ra[j].z, ra[j].w);
            uint2 st; st.x = *(unsigned*)&p0; st.y = *(unsigned*)&p1;
            *(uint2*)&As[(srow + 16 * j) * GST + c4 * 2] = st;
        }
#pragma unroll
        for (int j = 0; j < 4; ++j) {
            __half2 p0 = __floats2half2_rn(rb[j].x, rb[j].y);
            __half2 p1 = __floats2half2_rn(rb[j].z, rb[j].w);
            uint2 st; st.x = *(unsigned*)&p0; st.y = *(unsigned*)&p1;
            *(uint2*)&Bs[(srow + 16 * j) * GST + c4 * 2] = st;
        }
        __syncthreads();

        if (k0 + GBK < K) {
            const float* Ap = A + (size_t)bm * lda + k0 + GBK + c4 * 4;
            const float* Bp = B + (size_t)bn * ldb + k0 + GBK + c4 * 4;
#pragma unroll
            for (int j = 0; j < 8; ++j)
                ra[j] = *(const float4*)(Ap + (size_t)(srow + 16 * j) * lda);
#pragma unroll
            for (int j = 0; j < 4; ++j)
                rb[j] = *(const float4*)(Bp + (size_t)(srow + 16 * j) * ldb);
        }

#pragma unroll
        for (int ks = 0; ks < GBK / 16; ++ks) {
            int kw = ks * 8;
            unsigned a[2][4];
#pragma unroll
            for (int mf = 0; mf < 2; ++mf) {
                int base = wm + mf * 16;
                a[mf][0] = As[(base + r)     * GST + kw + m];
                a[mf][1] = As[(base + r + 8) * GST + kw + m];
                a[mf][2] = As[(base + r)     * GST + kw + m + 4];
                a[mf][3] = As[(base + r + 8) * GST + kw + m + 4];
            }
            unsigned bf[4][2];
#pragma unroll
            for (int nf = 0; nf < 4; ++nf) {
                int bas = (wn + nf * 8 + r) * GST + kw;
                bf[nf][0] = Bs[bas + m];
                bf[nf][1] = Bs[bas + m + 4];
            }
#pragma unroll
            for (int mf = 0; mf < 2; ++mf)
#pragma unroll
                for (int nf = 0; nf < 4; ++nf)
                    mma16816(acc[mf][nf][0], acc[mf][nf][1],
                             acc[mf][nf][2], acc[mf][nf][3],
                             a[mf][0], a[mf][1], a[mf][2], a[mf][3],
                             bf[nf][0], bf[nf][1]);
        }
        __syncthreads();
    }

#pragma unroll
    for (int mf = 0; mf < 2; ++mf) {
        int row = bm + wm + mf * 16 + r;
#pragma unroll
        for (int nf = 0; nf < 4; ++nf) {
            int col = bn + wn + nf * 8 + 2 * m;
            float2 bb = *(const float2*)(bias + col);
            float2 o0, o1;
            o0.x = acc[mf][nf][0] + bb.x;
            o0.y = acc[mf][nf][1] + bb.y;
            o1.x = acc[mf][nf][2] + bb.x;
            o1.y = acc[mf][nf][3] + bb.y;
            *(float2*)(C + (size_t)row * ldc + col)       = o0;
            *(float2*)(C + (size_t)(row + 8) * ldc + col) = o1;
        }
    }
}

__global__ void __launch_bounds__(256) hgemm_gx(
    const float* __restrict__ X,
    const float* __restrict__ Wu, const float* __restrict__ Wr,
    const float* __restrict__ Wc,
    const float* __restrict__ bu, const float* __restrict__ br,
    const float* __restrict__ bc)
{
    const float* B;
    const float* bias;
    if (blockIdx.z == 0)      { B = Wu; bias = bu; }
    else if (blockIdx.z == 1) { B = Wr; bias = br; }
    else                      { B = Wc; bias = bc; }
    hgemm_body(X, INF, B + HID, HID + INF, bias,
               &g_gx[blockIdx.z][0], HID, INF,
               blockIdx.y * GBM, blockIdx.x * GBN);
}

__global__ void __launch_bounds__(256) hgemm_y(
    const float* __restrict__ Hbuf, const float* __restrict__ Wy,
    const float* __restrict__ by, float* __restrict__ Yout)
{
    hgemm_body(Hbuf, HID, Wy, HID, by, Yout, OUT, HID,
               blockIdx.y * GBM, blockIdx.x * GBN);
}

// ---------------------------------------------------------------------------
// Tensor-core recurrent kernel — exact R11 structure (concentrated slots,
// plain syncthreads, single-chain mma) + staggered double-poll (only change).
// ---------------------------------------------------------------------------
#define REC_THREADS 512
#define REC_SMEM (196608 + 3264)

__global__ void __launch_bounds__(REC_THREADS, 1) gru_rec(
    const float* __restrict__ Wu, const float* __restrict__ Wr,
    const float* __restrict__ Wc, float* __restrict__ hid_out)
{
    extern __shared__ unsigned char smem_raw[];
    uint4* fragU = (uint4*)smem_raw;                 // [128 kt][32] uint4
    uint4* fragR = fragU + 128 * 32;
    uint4* fragC = fragR + 128 * 32;
    float* part_u = (float*)(fragC + 128 * 32);      // [16][16] (+pad)
    float* part_r = part_u + 272;
    float* part_c = part_r + 272;

    const int cta = blockIdx.x;
    const int tid = threadIdx.x;
    const int wid = tid >> 5;
    const int l   = tid & 31;
    const int m   = l & 3;
    const int row0 = cta << 4;

    // ---- Prologue: permute weights into A-fragment order (fp16) ----
    {
        const float* src[3] = {Wu, Wr, Wc};
        uint4* dst[3] = {fragU, fragR, fragC};
        for (int s = tid; s < 3 * 128 * 32; s += REC_THREADS) {
            int g   = s >> 12;
            int rem = s & 4095;
            int kt  = rem >> 5;
            int ln  = rem & 31;
            int rr  = ln >> 2;
            int k2  = kt * 16 + ((ln & 3) << 1);
            const float* W = src[g];
            const float* p00 = W + (size_t)(row0 + rr) * (HID + INF) + k2;
            const float* p10 = W + (size_t)(row0 + rr + 8) * (HID + INF) + k2;
            float2 v00 = *(const float2*)p00;
            float2 v10 = *(const float2*)p10;
            float2 v01 = *(const float2*)(p00 + 8);
            float2 v11 = *(const float2*)(p10 + 8);
            __half2 h00 = __floats2half2_rn(v00.x, v00.y);
            __half2 h10 = __floats2half2_rn(v10.x, v10.y);
            __half2 h01 = __floats2half2_rn(v01.x, v01.y);
            __half2 h11 = __floats2half2_rn(v11.x, v11.y);
            uint4 out;
            out.x = *(unsigned*)&h00;
            out.y = *(unsigned*)&h10;
            out.z = *(unsigned*)&h01;
            out.w = *(unsigned*)&h11;
            dst[g][kt * 32 + ln] = out;
        }
    }

    // ---- Initial publish: h0 = 0, tag 1 ----
    if (wid == 0 && l < 4)
        publish_slot(&g_hx[cta * 4 + l], 0u, 0u, 1u);
    __syncthreads();

    // warp0 lanes 0-15 carry fp32 state + all three gx values for own row
    float h_own = 0.f;
    float gxu_v = 0.f, gxr_v = 0.f, gxc_v = 0.f;
    if (wid == 0 && l < 16) {
        gxu_v = __ldcg(&g_gx[0][row0 + l]);
        gxr_v = __ldcg(&g_gx[1][row0 + l]);
        gxc_v = __ldcg(&g_gx[2][row0 + l]);
    }

    const int slot = 32 * wid + l;   // this lane's exchange slot (0..511)

    for (int t = 0; t < SEQ; ++t) {
        const unsigned tag = (unsigned)(t + 1);

        // ---- poll own h slot ----
        uint2 hs = poll_slot(&g_hx[slot], tag);

        // ---- r-only mma (critical path to rh publish) ----
        {
            float r0 = 0.f, r1 = 0.f, r2 = 0.f, r3 = 0.f;
            const uint4* fr = fragR + (wid * 8) * 32 + l;
#pragma unroll
            for (int i = 0; i < 8; ++i) {
                unsigned bx = __shfl_sync(FULL, hs.x, (i << 2) | m);
                unsigned by = __shfl_sync(FULL, hs.y, (i << 2) | m);
                uint4 ar = fr[i * 32];
                mma16816(r0, r1, r2, r3, ar.x, ar.y, ar.z, ar.w, bx, by);
            }
            if (m == 0) {
                part_r[wid * 16 + (l >> 2)]     = r0;
                part_r[wid * 16 + (l >> 2) + 8] = r2;
            }
        }
        __syncthreads();

        // ---- warp0: reduce r (half-split), publish r*h ----
        if (wid == 0) {
            const int rr = l & 15, hf = (l >> 4) * 8;
            float s = 0.f;
#pragma unroll
            for (int w8 = 0; w8 < 8; ++w8)
                s += part_r[(hf + w8) * 16 + rr];
            s += __shfl_xor_sync(FULL, s, 16);
            unsigned rh_bits = 0;
            if (l < 16) {
                float rg = 1.f / (1.f + __expf(-(s + gxr_v)));
                rh_bits = (unsigned)__half_as_ushort(__float2half(rg * h_own));
            }
            unsigned a = __shfl_sync(FULL, rh_bits, 2 * m);
            unsigned b = __shfl_sync(FULL, rh_bits, 1 + 2 * m);
            unsigned c = __shfl_sync(FULL, rh_bits, 8 + 2 * m);
            unsigned d = __shfl_sync(FULL, rh_bits, 9 + 2 * m);
            if (l < 4)
                publish_slot(&g_rhx[cta * 4 + l], a | (b << 16), c | (d << 16), tag);
        }

        // ---- u mma: overlaps the rh exchange flight ----
        {
            float u0 = 0.f, u1 = 0.f, u2 = 0.f, u3 = 0.f;
            const uint4* fu = fragU + (wid * 8) * 32 + l;
#pragma unroll
            for (int i = 0; i < 8; ++i) {
                unsigned bx = __shfl_sync(FULL, hs.x, (i << 2) | m);
                unsigned by = __shfl_sync(FULL, hs.y, (i << 2) | m);
                uint4 au = fu[i * 32];
                mma16816(u0, u1, u2, u3, au.x, au.y, au.z, au.w, bx, by);
            }
            if (m == 0) {
                part_u[wid * 16 + (l >> 2)]     = u0;
                part_u[wid * 16 + (l >> 2) + 8] = u2;
            }
        }

        // ---- poll own rh slot, then cand mma ----
        {
            uint2 rs = poll_slot(&g_rhx[slot], tag);
            float a0 = 0.f, a1 = 0.f, a2 = 0.f, a3 = 0.f;
            const uint4* fc = fragC + (wid * 8) * 32 + l;
#pragma unroll
            for (int i = 0; i < 8; ++i) {
                unsigned bx = __shfl_sync(FULL, rs.x, (i << 2) | m);
                unsigned by = __shfl_sync(FULL, rs.y, (i << 2) | m);
                uint4 ac = fc[i * 32];
                mma16816(a0, a1, a2, a3, ac.x, ac.y, ac.z, ac.w, bx, by);
            }
            if (m == 0) {
                part_c[wid * 16 + (l >> 2)]     = a0;
                part_c[wid * 16 + (l >> 2) + 8] = a2;
            }
        }
        __syncthreads();

        // ---- warp0: reduce u + cand (half-split), h update, publish h ----
        if (wid == 0) {
            const int rr = l & 15, hf = (l >> 4) * 8;
            float su = 0.f, sc = 0.f;
#pragma unroll
            for (int w8 = 0; w8 < 8; ++w8) {
                su += part_u[(hf + w8) * 16 + rr];
                sc += part_c[(hf + w8) * 16 + rr];
            }
            su += __shfl_xor_sync(FULL, su, 16);
            sc += __shfl_xor_sync(FULL, sc, 16);
            if (l < 16) {
                float u = 1.f / (1.f + __expf(-(su + gxu_v)));
                float e2x = __expf(2.f * (sc + gxc_v));
                float cand = 1.f - 2.f / (e2x + 1.f);    // tanh
                h_own = fmaf(u, cand - h_own, h_own);
            }
            unsigned hb = (l < 16)
                ? (unsigned)__half_as_ushort(__float2half(h_own)) : 0u;
            unsigned a = __shfl_sync(FULL, hb, 2 * m);
            unsigned b = __shfl_sync(FULL, hb, 1 + 2 * m);
            unsigned c = __shfl_sync(FULL, hb, 8 + 2 * m);
            unsigned d = __shfl_sync(FULL, hb, 9 + 2 * m);
            if (l < 4)
                publish_slot(&g_hx[cta * 4 + l], a | (b << 16), c | (d << 16),
                             tag + 1u);
            // off the critical path: output store + next-step gx prefetch
            if (l < 16) {
                hid_out[(size_t)t * HID + row0 + l] = h_own;
                if (t + 1 < SEQ) {
                    gxu_v = __ldcg(&g_gx[0][(size_t)(t + 1) * HID + row0 + l]);
                    gxr_v = __ldcg(&g_gx[1][(size_t)(t + 1) * HID + row0 + l]);
                    gxc_v = __ldcg(&g_gx[2][(size_t)(t + 1) * HID + row0 + l]);
                }
            }
        }
        // loop top: every lane polls h slots for tag t+2
    }
}

// ---------------------------------------------------------------------------
extern "C" void kernel_launch(void* const* d_in, const int* in_sizes, int n_in,
                              void* d_out, int out_size)
{
    const float* X  = (const float*)d_in[0];
    const float* Wu = (const float*)d_in[1];
    const float* bu = (const float*)d_in[2];
    const float* Wr = (const float*)d_in[3];
    const float* br = (const float*)d_in[4];
    const float* Wc = (const float*)d_in[5];
    const float* bc = (const float*)d_in[6];
    const float* Wy = (const float*)d_in[7];
    const float* by = (const float*)d_in[8];

    float* outputs = (float*)d_out;                       // (SEQ, OUT)
    float* hidden  = (float*)d_out + (size_t)SEQ * OUT;   // (SEQ, HID)

    static bool attr_set = false;
    if (!attr_set) {
        cudaFuncSetAttribute(gru_rec, cudaFuncAttributeMaxDynamicSharedMemorySize,
                             REC_SMEM);
        attr_set = true;
    }

    // 0) Reset slot tags (graph-replay determinism)
    reset_state<<<2, 256>>>();

    // 1) Gx_j = X @ Wx_j^T + b_j   (tensor-core fp16 GEMM, reg-pipelined)
    dim3 g1(HID / GBN, SEQ / GBM, 3);
    hgemm_gx<<<g1, 256>>>(X, Wu, Wr, Wc, bu, br, bc);

    // 2) Sequential recurrence (persistent kernel, R11 exchange + double-poll)
    gru_rec<<<NCTA, REC_THREADS, REC_SMEM>>>(Wu, Wr, Wc, hidden);

    // 3) outputs = hidden @ W_y^T + b_y   (tensor-core fp16 GEMM)
    dim3 g2(OUT / GBN, SEQ / GBM);
    hgemm_y<<<g2, 256>>>(hidden, Wy, by, outputs);
}

// round 15
// speedup vs baseline: 1.3118x; 1.3118x over previous
#include <cuda_runtime.h>
#include <cuda_fp16.h>
#include <cstdint>

#define SEQ 2048
#define INF 1024
#define HID 2048
#define OUT 1024
#define NCTA 128
#define FULL 0xffffffffu

// Scratch (device globals — allocation-free per harness rules)
__device__ float g_gx[3][(size_t)SEQ * HID];  // precomputed Wx@x_t + b, per gate
// Flag-in-data exchange slots (CONCENTRATED layout — measured optimum, R11).
// Slot s = (b, m): b = producer CTA, m = 0..3.
// uint4 = {lo, tag, hi, tag}: lo = halves {16b+2m, 16b+2m+1},
//                             hi = halves {16b+2m+8, 16b+2m+9}
__device__ uint4 g_hx[NCTA * 4];    // h exchange   (tag = t+1 for step-t use)
__device__ uint4 g_rhx[NCTA * 4];   // r*h exchange (tag = t+1 at step t)

// ---------------------------------------------------------------------------
__global__ void reset_state() {   // zero all slot tags each launch (replay-safe)
    int i = blockIdx.x * blockDim.x + threadIdx.x;
    if (i < NCTA * 4) {
        g_hx[i]  = make_uint4(0u, 0u, 0u, 0u);
        g_rhx[i] = make_uint4(0u, 0u, 0u, 0u);
    }
}

// Tight self-paced poll (R11-proven optimum): one dependent load per RT.
__device__ __forceinline__ uint2 poll_slot(const uint4* p, unsigned tag) {
    unsigned x, y, z, w;
    do {
        asm volatile("ld.relaxed.gpu.global.v4.b32 {%0,%1,%2,%3}, [%4];"
                     : "=r"(x), "=r"(y), "=r"(z), "=r"(w) : "l"(p) : "memory");
    } while (y != tag || w != tag);
    return make_uint2(x, z);
}

__device__ __forceinline__ void publish_slot(uint4* p, unsigned lo, unsigned hi,
                                             unsigned tag) {
    asm volatile("st.release.gpu.global.v4.b32 [%0], {%1,%2,%3,%4};"
                 :: "l"(p), "r"(lo), "r"(tag), "r"(hi), "r"(tag) : "memory");
}

__device__ __forceinline__ void mma16816(
    float& c0, float& c1, float& c2, float& c3,
    unsigned a0, unsigned a1, unsigned a2, unsigned a3,
    unsigned b0, unsigned b1)
{
    asm volatile(
        "mma.sync.aligned.m16n8k16.row.col.f32.f16.f16.f32 "
        "{%0,%1,%2,%3}, {%4,%5,%6,%7}, {%8,%9}, {%0,%1,%2,%3};"
        : "+f"(c0), "+f"(c1), "+f"(c2), "+f"(c3)
        : "r"(a0), "r"(a1), "r"(a2), "r"(a3), "r"(b0), "r"(b1));
}

// ---------------------------------------------------------------------------
// fp16 tensor-core GEMM with register-pipelined staging (R13-proven).
// ---------------------------------------------------------------------------
#define GBM 128
#define GBN 64
#define GBK 64
#define GST 36

__device__ __forceinline__ void hgemm_body(
    const float* __restrict__ A, int lda,
    const float* __restrict__ B, int ldb,
    const float* __restrict__ bias,
    float* __restrict__ C, int ldc, int K,
    int bm, int bn)
{
    __shared__ unsigned As[GBM * GST];
    __shared__ unsigned Bs[GBN * GST];

    const int tid = threadIdx.x;
    const int wid = tid >> 5;
    const int l   = tid & 31;
    const int r   = l >> 2;
    const int m   = l & 3;
    const int wm  = (wid & 3) * 32;
    const int wn  = (wid >> 2) * 32;
    const int srow = tid >> 4;
    const int c4   = tid & 15;

    float acc[2][4][4];
#pragma unroll
    for (int i = 0; i < 2; ++i)
#pragma unroll
        for (int j = 0; j < 4; ++j)
#pragma unroll
            for (int k = 0; k < 4; ++k) acc[i][j][k] = 0.f;

    float4 ra[8];
    float4 rb[4];

#pragma unroll
    for (int j = 0; j < 8; ++j)
        ra[j] = *(const float4*)(A + (size_t)(bm + srow + 16 * j) * lda + c4 * 4);
#pragma unroll
    for (int j = 0; j < 4; ++j)
        rb[j] = *(const float4*)(B + (size_t)(bn + srow + 16 * j) * ldb + c4 * 4);

    for (int k0 = 0; k0 < K; k0 += GBK) {
#pragma unroll
        for (int j = 0; j < 8; ++j) {
            __half2 p0 = __floats2half2_rn(ra[j].x, ra[j].y);
            __half2 p1 = __floats2half2_rn(ra[j].z, ra[j].w);
            uint2 st; st.x = *(unsigned*)&p0; st.y = *(unsigned*)&p1;
            *(uint2*)&As[(srow + 16 * j) * GST + c4 * 2] = st;
        }
#pragma unroll
        for (int j = 0; j < 4; ++j) {
            __half2 p0 = __floats2half2_rn(rb[j].x, rb[j].y);
            __half2 p1 = __floats2half2_rn(rb[j].z, rb[j].w);
            uint2 st; st.x = *(unsigned*)&p0; st.y = *(unsigned*)&p1;
            *(uint2*)&Bs[(srow + 16 * j) * GST + c4 * 2] = st;
        }
        __syncthreads();

        if (k0 + GBK < K) {
            const float* Ap = A + (size_t)bm * lda + k0 + GBK + c4 * 4;
            const float* Bp = B + (size_t)bn * ldb + k0 + GBK + c4 * 4;
#pragma unroll
            for (int j = 0; j < 8; ++j)
                ra[j] = *(const float4*)(Ap + (size_t)(srow + 16 * j) * lda);
#pragma unroll
            for (int j = 0; j < 4; ++j)
                rb[j] = *(const float4*)(Bp + (size_t)(srow + 16 * j) * ldb);
        }

#pragma unroll
        for (int ks = 0; ks < GBK / 16; ++ks) {
            int kw = ks * 8;
            unsigned a[2][4];
#pragma unroll
            for (int mf = 0; mf < 2; ++mf) {
                int base = wm + mf * 16;
                a[mf][0] = As[(base + r)     * GST + kw + m];
                a[mf][1] = As[(base + r + 8) * GST + kw + m];
                a[mf][2] = As[(base + r)     * GST + kw + m + 4];
                a[mf][3] = As[(base + r + 8) * GST + kw + m + 4];
            }
            unsigned bf[4][2];
#pragma unroll
            for (int nf = 0; nf < 4; ++nf) {
                int bas = (wn + nf * 8 + r) * GST + kw;
                bf[nf][0] = Bs[bas + m];
                bf[nf][1] = Bs[bas + m + 4];
            }
#pragma unroll
            for (int mf = 0; mf < 2; ++mf)
#pragma unroll
                for (int nf = 0; nf < 4; ++nf)
                    mma16816(acc[mf][nf][0], acc[mf][nf][1],
                             acc[mf][nf][2], acc[mf][nf][3],
                             a[mf][0], a[mf][1], a[mf][2], a[mf][3],
                             bf[nf][0], bf[nf][1]);
        }
        __syncthreads();
    }

#pragma unroll
    for (int mf = 0; mf < 2; ++mf) {
        int row = bm + wm + mf * 16 + r;
#pragma unroll
        for (int nf = 0; nf < 4; ++nf) {
            int col = bn + wn + nf * 8 + 2 * m;
            float2 bb = *(const float2*)(bias + col);
            float2 o0, o1;
            o0.x = acc[mf][nf][0] + bb.x;
            o0.y = acc[mf][nf][1] + bb.y;
            o1.x = acc[mf][nf][2] + bb.x;
            o1.y = acc[mf][nf][3] + bb.y;
            *(float2*)(C + (size_t)row * ldc + col)       = o0;
            *(float2*)(C + (size_t)(row + 8) * ldc + col) = o1;
        }
    }
}

__global__ void __launch_bounds__(256) hgemm_gx(
    const float* __restrict__ X,
    const float* __restrict__ Wu, const float* __restrict__ Wr,
    const float* __restrict__ Wc,
    const float* __restrict__ bu, const float* __restrict__ br,
    const float* __restrict__ bc)
{
    const float* B;
    const float* bias;
    if (blockIdx.z == 0)      { B = Wu; bias = bu; }
    else if (blockIdx.z == 1) { B = Wr; bias = br; }
    else                      { B = Wc; bias = bc; }
    hgemm_body(X, INF, B + HID, HID + INF, bias,
               &g_gx[blockIdx.z][0], HID, INF,
               blockIdx.y * GBM, blockIdx.x * GBN);
}

__global__ void __launch_bounds__(256) hgemm_y(
    const float* __restrict__ Hbuf, const float* __restrict__ Wy,
    const float* __restrict__ by, float* __restrict__ Yout)
{
    hgemm_body(Hbuf, HID, Wy, HID, by, Yout, OUT, HID,
               blockIdx.y * GBM, blockIdx.x * GBN);
}

// ---------------------------------------------------------------------------
// Tensor-core recurrent kernel — R11 structure verbatim (measured optimum):
// concentrated slots, tight self-paced polls, plain syncthreads, r-first.
// ---------------------------------------------------------------------------
#define REC_THREADS 512
#define REC_SMEM (196608 + 3264)

__global__ void __launch_bounds__(REC_THREADS, 1) gru_rec(
    const float* __restrict__ Wu, const float* __restrict__ Wr,
    const float* __restrict__ Wc, float* __restrict__ hid_out)
{
    extern __shared__ unsigned char smem_raw[];
    uint4* fragU = (uint4*)smem_raw;                 // [128 kt][32] uint4
    uint4* fragR = fragU + 128 * 32;
    uint4* fragC = fragR + 128 * 32;
    float* part_u = (float*)(fragC + 128 * 32);      // [16][16] (+pad)
    float* part_r = part_u + 272;
    float* part_c = part_r + 272;

    const int cta = blockIdx.x;
    const int tid = threadIdx.x;
    const int wid = tid >> 5;
    const int l   = tid & 31;
    const int m   = l & 3;
    const int row0 = cta << 4;

    // ---- Prologue: permute weights into A-fragment order (fp16) ----
    {
        const float* src[3] = {Wu, Wr, Wc};
        uint4* dst[3] = {fragU, fragR, fragC};
        for (int s = tid; s < 3 * 128 * 32; s += REC_THREADS) {
            int g   = s >> 12;
            int rem = s & 4095;
            int kt  = rem >> 5;
            int ln  = rem & 31;
            int rr  = ln >> 2;
            int k2  = kt * 16 + ((ln & 3) << 1);
            const float* W = src[g];
            const float* p00 = W + (size_t)(row0 + rr) * (HID + INF) + k2;
            const float* p10 = W + (size_t)(row0 + rr + 8) * (HID + INF) + k2;
            float2 v00 = *(const float2*)p00;
            float2 v10 = *(const float2*)p10;
            float2 v01 = *(const float2*)(p00 + 8);
            float2 v11 = *(const float2*)(p10 + 8);
            __half2 h00 = __floats2half2_rn(v00.x, v00.y);
            __half2 h10 = __floats2half2_rn(v10.x, v10.y);
            __half2 h01 = __floats2half2_rn(v01.x, v01.y);
            __half2 h11 = __floats2half2_rn(v11.x, v11.y);
            uint4 out;
            out.x = *(unsigned*)&h00;
            out.y = *(unsigned*)&h10;
            out.z = *(unsigned*)&h01;
            out.w = *(unsigned*)&h11;
            dst[g][kt * 32 + ln] = out;
        }
    }

    // ---- Initial publish: h0 = 0, tag 1 ----
    if (wid == 0 && l < 4)
        publish_slot(&g_hx[cta * 4 + l], 0u, 0u, 1u);
    __syncthreads();

    // warp0 lanes 0-15 carry fp32 state + all three gx values for own row
    float h_own = 0.f;
    float gxu_v = 0.f, gxr_v = 0.f, gxc_v = 0.f;
    if (wid == 0 && l < 16) {
        gxu_v = __ldcg(&g_gx[0][row0 + l]);
        gxr_v = __ldcg(&g_gx[1][row0 + l]);
        gxc_v = __ldcg(&g_gx[2][row0 + l]);
    }

    const int slot = 32 * wid + l;   // this lane's exchange slot (0..511)

    for (int t = 0; t < SEQ; ++t) {
        const unsigned tag = (unsigned)(t + 1);

        // ---- poll own h slot ----
        uint2 hs = poll_slot(&g_hx[slot], tag);

        // ---- r-only mma (critical path to rh publish) ----
        {
            float r0 = 0.f, r1 = 0.f, r2 = 0.f, r3 = 0.f;
            const uint4* fr = fragR + (wid * 8) * 32 + l;
#pragma unroll
            for (int i = 0; i < 8; ++i) {
                unsigned bx = __shfl_sync(FULL, hs.x, (i << 2) | m);
                unsigned by = __shfl_sync(FULL, hs.y, (i << 2) | m);
                uint4 ar = fr[i * 32];
                mma16816(r0, r1, r2, r3, ar.x, ar.y, ar.z, ar.w, bx, by);
            }
            if (m == 0) {
                part_r[wid * 16 + (l >> 2)]     = r0;
                part_r[wid * 16 + (l >> 2) + 8] = r2;
            }
        }
        __syncthreads();

        // ---- warp0: reduce r (half-split), publish r*h ----
        if (wid == 0) {
            const int rr = l & 15, hf = (l >> 4) * 8;
            float s = 0.f;
#pragma unroll
            for (int w8 = 0; w8 < 8; ++w8)
                s += part_r[(hf + w8) * 16 + rr];
            s += __shfl_xor_sync(FULL, s, 16);
            unsigned rh_bits = 0;
            if (l < 16) {
                float rg = 1.f / (1.f + __expf(-(s + gxr_v)));
                rh_bits = (unsigned)__half_as_ushort(__float2half(rg * h_own));
            }
            unsigned a = __shfl_sync(FULL, rh_bits, 2 * m);
            unsigned b = __shfl_sync(FULL, rh_bits, 1 + 2 * m);
            unsigned c = __shfl_sync(FULL, rh_bits, 8 + 2 * m);
            unsigned d = __shfl_sync(FULL, rh_bits, 9 + 2 * m);
            if (l < 4)
                publish_slot(&g_rhx[cta * 4 + l], a | (b << 16), c | (d << 16), tag);
        }

        // ---- u mma: overlaps the rh exchange flight ----
        {
            float u0 = 0.f, u1 = 0.f, u2 = 0.f, u3 = 0.f;
            const uint4* fu = fragU + (wid * 8) * 32 + l;
#pragma unroll
            for (int i = 0; i < 8; ++i) {
                unsigned bx = __shfl_sync(FULL, hs.x, (i << 2) | m);
                unsigned by = __shfl_sync(FULL, hs.y, (i << 2) | m);
                uint4 au = fu[i * 32];
                mma16816(u0, u1, u2, u3, au.x, au.y, au.z, au.w, bx, by);
            }
            if (m == 0) {
                part_u[wid * 16 + (l >> 2)]     = u0;
                part_u[wid * 16 + (l >> 2) + 8] = u2;
            }
        }

        // ---- poll own rh slot, then cand mma ----
        {
            uint2 rs = poll_slot(&g_rhx[slot], tag);
            float a0 = 0.f, a1 = 0.f, a2 = 0.f, a3 = 0.f;
            const uint4* fc = fragC + (wid * 8) * 32 + l;
#pragma unroll
            for (int i = 0; i < 8; ++i) {
                unsigned bx = __shfl_sync(FULL, rs.x, (i << 2) | m);
                unsigned by = __shfl_sync(FULL, rs.y, (i << 2) | m);
                uint4 ac = fc[i * 32];
                mma16816(a0, a1, a2, a3, ac.x, ac.y, ac.z, ac.w, bx, by);
            }
            if (m == 0) {
                part_c[wid * 16 + (l >> 2)]     = a0;
                part_c[wid * 16 + (l >> 2) + 8] = a2;
            }
        }
        __syncthreads();

        // ---- warp0: reduce u + cand (half-split), h update, publish h ----
        if (wid == 0) {
            const int rr = l & 15, hf = (l >> 4) * 8;
            float su = 0.f, sc = 0.f;
#pragma unroll
            for (int w8 = 0; w8 < 8; ++w8) {
                su += part_u[(hf + w8) * 16 + rr];
                sc += part_c[(hf + w8) * 16 + rr];
            }
            su += __shfl_xor_sync(FULL, su, 16);
            sc += __shfl_xor_sync(FULL, sc, 16);
            if (l < 16) {
                float u = 1.f / (1.f + __expf(-(su + gxu_v)));
                float e2x = __expf(2.f * (sc + gxc_v));
                float cand = 1.f - 2.f / (e2x + 1.f);    // tanh
                h_own = fmaf(u, cand - h_own, h_own);
            }
            unsigned hb = (l < 16)
                ? (unsigned)__half_as_ushort(__float2half(h_own)) : 0u;
            unsigned a = __shfl_sync(FULL, hb, 2 * m);
            unsigned b = __shfl_sync(FULL, hb, 1 + 2 * m);
            unsigned c = __shfl_sync(FULL, hb, 8 + 2 * m);
            unsigned d = __shfl_sync(FULL, hb, 9 + 2 * m);
            if (l < 4)
                publish_slot(&g_hx[cta * 4 + l], a | (b << 16), c | (d << 16),
                             tag + 1u);
            // off the critical path: output store + next-step gx prefetch
            if (l < 16) {
                hid_out[(size_t)t * HID + row0 + l] = h_own;
                if (t + 1 < SEQ) {
                    gxu_v = __ldcg(&g_gx[0][(size_t)(t + 1) * HID + row0 + l]);
                    gxr_v = __ldcg(&g_gx[1][(size_t)(t + 1) * HID + row0 + l]);
                    gxc_v = __ldcg(&g_gx[2][(size_t)(t + 1) * HID + row0 + l]);
                }
            }
        }
        // loop top: every lane polls h slots for tag t+2
    }
}

// ---------------------------------------------------------------------------
extern "C" void kernel_launch(void* const* d_in, const int* in_sizes, int n_in,
                              void* d_out, int out_size)
{
    const float* X  = (const float*)d_in[0];
    const float* Wu = (const float*)d_in[1];
    const float* bu = (const float*)d_in[2];
    const float* Wr = (const float*)d_in[3];
    const float* br = (const float*)d_in[4];
    const float* Wc = (const float*)d_in[5];
    const float* bc = (const float*)d_in[6];
    const float* Wy = (const float*)d_in[7];
    const float* by = (const float*)d_in[8];

    float* outputs = (float*)d_out;                       // (SEQ, OUT)
    float* hidden  = (float*)d_out + (size_t)SEQ * OUT;   // (SEQ, HID)

    static bool attr_set = false;
    if (!attr_set) {
        cudaFuncSetAttribute(gru_rec, cudaFuncAttributeMaxDynamicSharedMemorySize,
                             REC_SMEM);
        attr_set = true;
    }

    // 0) Reset slot tags (graph-replay determinism)
    reset_state<<<2, 256>>>();

    // 1) Gx_j = X @ Wx_j^T + b_j   (tensor-core fp16 GEMM, reg-pipelined)
    dim3 g1(HID / GBN, SEQ / GBM, 3);
    hgemm_gx<<<g1, 256>>>(X, Wu, Wr, Wc, bu, br, bc);

    // 2) Sequential recurrence (persistent kernel, R11-optimum exchange)
    gru_rec<<<NCTA, REC_THREADS, REC_SMEM>>>(Wu, Wr, Wc, hidden);

    // 3) outputs = hidden @ W_y^T + b_y   (tensor-core fp16 GEMM)
    dim3 g2(OUT / GBN, SEQ / GBM);
    hgemm_y<<<g2, 256>>>(hidden, Wy, by, outputs);
}